// round 5
// baseline (speedup 1.0000x reference)
#include <cuda_runtime.h>

#define H_IN   200
#define W_IN   320
#define C_IN   64
#define H_OUT  48
#define W_OUT  320

#define SRC_CH_STRIDE (H_IN * W_IN)    // 64000 floats
#define DST_CH_STRIDE (H_OUT * W_OUT)  // 15360 floats

__global__ void __launch_bounds__(W_OUT)
roi_crop_kernel(const float* __restrict__ x,
                const int*   __restrict__ bboxes,
                const int*   __restrict__ box_img,
                float*       __restrict__ out)
{
    const int j = threadIdx.x;   // output column, 0..319 (warp = 32 consecutive j)
    const int i = blockIdx.x;    // output row, 0..47
    const int b = blockIdx.y;    // box, 0..255

    // bbox params: uniform across block, broadcast loads
    int x0 = __ldg(&bboxes[b * 4 + 0]);
    int y0 = __ldg(&bboxes[b * 4 + 1]);
    int x1 = __ldg(&bboxes[b * 4 + 2]);
    int y1 = __ldg(&bboxes[b * 4 + 3]);
    x0 = min(max(x0, 0), W_IN - 1);
    y0 = min(max(y0, 0), H_IN - 1);
    x1 = min(max(x1, 0), W_IN - 1);
    y1 = min(max(y1, 0), H_IN - 1);
    x1 = max(x1, x0);
    y1 = max(y1, y0);
    const int h = y1 - y0 + 1;
    const int w = x1 - x0 + 1;

    const int r   = y0 + (i * h) / H_OUT;   // source row (uniform per block)
    const int col = x0 + (j * w) / W_OUT;   // source col (non-decreasing, step<=1)

    const int img = __ldg(&box_img[b]);

    const float* __restrict__ src =
        x + (size_t)img * (C_IN * SRC_CH_STRIDE) + (size_t)r * W_IN + col;
    float* __restrict__ dst =
        out + (size_t)b * (C_IN * DST_CH_STRIDE) + (size_t)i * W_OUT + j;

    // Channel loop: gather index is channel-invariant; only constant strides.
    // Unroll 16 -> 16 independent loads in flight, immediate-offset addressing.
    #pragma unroll 16
    for (int c = 0; c < C_IN; c++) {
        dst[c * DST_CH_STRIDE] = __ldg(src + c * SRC_CH_STRIDE);
    }
}

extern "C" void kernel_launch(void* const* d_in, const int* in_sizes, int n_in,
                              void* d_out, int out_size)
{
    const float* x       = (const float*)d_in[0];
    const int*   bboxes  = (const int*)d_in[1];
    const int*   box_img = (const int*)d_in[2];
    float*       out     = (float*)d_out;

    dim3 grid(H_OUT, 256);        // (48 rows, 256 boxes)
    roi_crop_kernel<<<grid, W_OUT>>>(x, bboxes, box_img, out);
}

// round 7
// speedup vs baseline: 1.0025x; 1.0025x over previous
#include <cuda_runtime.h>

#define H_IN   200
#define W_IN   320
#define C_IN   64
#define H_OUT  48
#define W_OUT  320

#define SRC_CH_STRIDE (H_IN * W_IN)    // 64000 floats
#define DST_CH_STRIDE (H_OUT * W_OUT)  // 15360 floats

#define QUADS      (W_OUT / 4)         // 80 column-quads per row
#define CGROUPS    4                   // channel groups
#define CH_PER_CG  (C_IN / CGROUPS)    // 16 channels per group
#define NTHREADS   (QUADS * CGROUPS)   // 320

__global__ void __launch_bounds__(NTHREADS)
roi_crop_kernel(const float* __restrict__ x,
                const int*   __restrict__ bboxes,
                const int*   __restrict__ box_img,
                float*       __restrict__ out)
{
    const int t  = threadIdx.x;        // 0..319
    const int q  = t % QUADS;          // column quad -> j0 = 4q
    const int cg = t / QUADS;          // channel group 0..3
    const int i  = blockIdx.x;         // output row 0..47
    const int b  = blockIdx.y;         // box 0..255

    // bbox params: uniform across block (broadcast loads)
    int x0 = __ldg(&bboxes[b * 4 + 0]);
    int y0 = __ldg(&bboxes[b * 4 + 1]);
    int x1 = __ldg(&bboxes[b * 4 + 2]);
    int y1 = __ldg(&bboxes[b * 4 + 3]);
    x0 = min(max(x0, 0), W_IN - 1);
    y0 = min(max(y0, 0), H_IN - 1);
    x1 = min(max(x1, 0), W_IN - 1);
    y1 = min(max(y1, 0), H_IN - 1);
    x1 = max(x1, x0);
    y1 = max(y1, y0);
    const int h = y1 - y0 + 1;
    const int w = x1 - x0 + 1;

    const int r  = y0 + (i * h) / H_OUT;     // source row (uniform per block)
    const int j0 = q * 4;
    // 4 source columns (non-decreasing, step <= 1); const-divisor -> mul/shift
    const int col0 = x0 + ((j0 + 0) * w) / W_OUT;
    const int col1 = x0 + ((j0 + 1) * w) / W_OUT;
    const int col2 = x0 + ((j0 + 2) * w) / W_OUT;
    const int col3 = x0 + ((j0 + 3) * w) / W_OUT;

    const int img = __ldg(&box_img[b]);

    const int c0 = cg * CH_PER_CG;
    const float* __restrict__ src =
        x + (size_t)img * (C_IN * SRC_CH_STRIDE)
          + (size_t)c0 * SRC_CH_STRIDE + (size_t)r * W_IN;
    float* __restrict__ dst =
        out + (size_t)b * (C_IN * DST_CH_STRIDE)
            + (size_t)c0 * DST_CH_STRIDE + (size_t)i * W_OUT + j0;

    // 16 channels: gather cols are channel-invariant; only constant strides.
    // Wide streaming stores (evict-first) keep the output stream out of L2.
    #pragma unroll
    for (int k = 0; k < CH_PER_CG; k++) {
        const float* __restrict__ s = src + k * SRC_CH_STRIDE;
        float4 v;
        v.x = __ldg(s + col0);
        v.y = __ldg(s + col1);
        v.z = __ldg(s + col2);
        v.w = __ldg(s + col3);
        __stcs((float4*)(dst + k * DST_CH_STRIDE), v);
    }
}

extern "C" void kernel_launch(void* const* d_in, const int* in_sizes, int n_in,
                              void* d_out, int out_size)
{
    const float* x       = (const float*)d_in[0];
    const int*   bboxes  = (const int*)d_in[1];
    const int*   box_img = (const int*)d_in[2];
    float*       out     = (float*)d_out;

    dim3 grid(H_OUT, 256);            // (48 rows, 256 boxes)
    roi_crop_kernel<<<grid, NTHREADS>>>(x, bboxes, box_img, out);
}

// round 8
// speedup vs baseline: 1.2318x; 1.2288x over previous
#include <cuda_runtime.h>

#define H_IN   200
#define W_IN   320
#define C_IN   64
#define H_OUT  48
#define W_OUT  320

#define SRC_CH_STRIDE (H_IN * W_IN)    // 64000 floats
#define DST_CH_STRIDE (H_OUT * W_OUT)  // 15360 floats

#define QUADS     (W_OUT / 4)          // 80 column-quads per row
#define NTHREADS  256
#define NUNITS    (H_OUT * QUADS)      // 3840 float4 units per (box,channel) tile

__global__ void __launch_bounds__(NTHREADS)
roi_crop_kernel(const float* __restrict__ x,
                const int*   __restrict__ bboxes,
                const int*   __restrict__ box_img,
                float*       __restrict__ out)
{
    const int c = blockIdx.x;    // channel 0..63
    const int b = blockIdx.y;    // box 0..255
    const int t = threadIdx.x;   // 0..255

    __shared__ int4 s_colq[QUADS];   // 4 source cols per output quad
    __shared__ int  s_row[H_OUT];    // source row per output row

    // bbox decode (uniform per block)
    int x0 = __ldg(&bboxes[b * 4 + 0]);
    int y0 = __ldg(&bboxes[b * 4 + 1]);
    int x1 = __ldg(&bboxes[b * 4 + 2]);
    int y1 = __ldg(&bboxes[b * 4 + 3]);
    x0 = min(max(x0, 0), W_IN - 1);
    y0 = min(max(y0, 0), H_IN - 1);
    x1 = min(max(x1, 0), W_IN - 1);
    y1 = min(max(y1, 0), H_IN - 1);
    x1 = max(x1, x0);
    y1 = max(y1, y0);
    const int h = y1 - y0 + 1;
    const int w = x1 - x0 + 1;

    if (t < QUADS) {                         // 80 threads fill column quads
        const int j0 = t * 4;
        int4 cq;
        cq.x = x0 + ((j0 + 0) * w) / W_OUT;  // const-divisor -> mul/shift
        cq.y = x0 + ((j0 + 1) * w) / W_OUT;
        cq.z = x0 + ((j0 + 2) * w) / W_OUT;
        cq.w = x0 + ((j0 + 3) * w) / W_OUT;
        s_colq[t] = cq;
    }
    if (t >= 128 && t < 128 + H_OUT)         // 48 threads fill row map
        s_row[t - 128] = y0 + ((t - 128) * h) / H_OUT;
    __syncthreads();

    const int img = __ldg(&box_img[b]);
    const float* __restrict__ src =
        x + (size_t)img * (C_IN * SRC_CH_STRIDE) + (size_t)c * SRC_CH_STRIDE;
    // This block's output tile: 61440 bytes, written fully sequentially.
    float4* __restrict__ dst =
        (float4*)(out + ((size_t)b * C_IN + c) * DST_CH_STRIDE);

    // 3840 units / 256 threads = 15 iterations; consecutive threads write
    // consecutive float4s -> block-linear DRAM write stream.
    #pragma unroll 5
    for (int u = t; u < NUNITS; u += NTHREADS) {
        const int i = u / QUADS;             // output row
        const int q = u - i * QUADS;         // quad within row
        const int4 cq = s_colq[q];           // LDS.128, conflict-free
        const float* __restrict__ s = src + s_row[i] * W_IN;
        float4 v;
        v.x = __ldg(s + cq.x);
        v.y = __ldg(s + cq.y);
        v.z = __ldg(s + cq.z);
        v.w = __ldg(s + cq.w);
        dst[u] = v;
    }
}

extern "C" void kernel_launch(void* const* d_in, const int* in_sizes, int n_in,
                              void* d_out, int out_size)
{
    const float* x       = (const float*)d_in[0];
    const int*   bboxes  = (const int*)d_in[1];
    const int*   box_img = (const int*)d_in[2];
    float*       out     = (float*)d_out;

    dim3 grid(C_IN, 256);                 // (64 channels, 256 boxes)
    roi_crop_kernel<<<grid, NTHREADS>>>(x, bboxes, box_img, out);
}